// round 16
// baseline (speedup 1.0000x reference)
#include <cuda_runtime.h>
#include <cstdint>
#include <math.h>

// Problem constants
#define Bp   4096
#define Dd   19
#define Ff   64
#define NCc  256
#define HIDh 32
#define SQq  16
#define Nn   (Bp + NCc)
#define PD   20            // padded row stride (19 + 1 zero pad)
#define PD4  5             // PD/4 (float4 granules)

// P2 tiling: task = (jt, oct of 16 j's). Lane = center. Static 2 tasks/block.
#define JT   128
#define NJT  (Nn / JT)      // 34
#define NPJT (Bp / JT)      // 32 patient-only tiles
#define NTASK (NJT * 8)     // 272 (16-j octants)
#define NSLOT (2 * 148)     // 296 y-partial slots: (block, j-half)

// P1 chunking
#define XCH   128                    // x rows per chunk
#define XPADW 68                     // padded smem row stride (floats)
#define NCHUNK ((Bp * Dd) / XCH)     // 608

// Persistent grid
#define NBLK 148
#define NTHR 512
#define NT_ALL (NBLK * NTHR)       // 75776

// Output offsets (floats)
#define OUT_GS  0
#define OUT_GE  (Bp * Dd)
#define OUT_GPE ((Bp + NCc) * Dd)
#define OUT_GL  (((2 * Bp) + NCc) * Dd)

typedef unsigned long long u64;

// -------- device scratch (no allocations allowed) --------
__device__ float4 g_x4[Nn * PD4];
__device__ float4 g_e4[Nn * PD4];
__device__ float4 g_party4[NSLOT * NCc * PD4];  // y-partials [slot][center][5]
__device__ u64    g_key8[(size_t)Bp * 8];       // [patient][wc-group] partial keys
__device__ float  g_ge[NCc * Dd];
__device__ float  g_sc[NCc * Dd];

// grid barrier state (zero-init at load; returns to steady state each run)
__device__ unsigned g_cnt[8];
__device__ unsigned g_cnt_root;
__device__ volatile unsigned g_bar_sense;

// Two-level sense-reversal barrier: 8 group counters -> root counter.
__device__ __forceinline__ void grid_barrier(unsigned* sense0) {
    __syncthreads();
    if (threadIdx.x == 0) {
        unsigned next = *sense0 ^ 1u;
        __threadfence();                       // publish this block's writes
        int g = blockIdx.x & 7;
        unsigned gsz = (g < 4) ? 19u : 18u;    // 148 = 4*19 + 4*18
        if (atomicAdd(&g_cnt[g], 1u) == gsz - 1u) {
            if (atomicAdd(&g_cnt_root, 1u) == 7u) {
                g_cnt_root = 0u;
                #pragma unroll
                for (int i = 0; i < 8; i++) g_cnt[i] = 0u;
                __threadfence();
                g_bar_sense = next;
            }
        }
        while (g_bar_sense != next) { }
        __threadfence();                       // acquire side
        *sense0 = next;
    }
    __syncthreads();
}

// packed f32x2 fma: d = a*b + d
__device__ __forceinline__ void ffma2(u64& d, u64 a, u64 b) {
    asm("fma.rn.f32x2 %0, %1, %2, %0;" : "+l"(d) : "l"(a), "l"(b));
}
__device__ __forceinline__ float lo32(u64 v) {
    return __uint_as_float((unsigned)(v & 0xFFFFFFFFull));
}
__device__ __forceinline__ float hi32(u64 v) {
    return __uint_as_float((unsigned)(v >> 32));
}
__device__ __forceinline__ u64 pack2(float a, float b) {
    u64 r;
    asm("mov.b64 %0, {%1, %2};" : "=l"(r) : "r"(__float_as_uint(a)), "r"(__float_as_uint(b)));
    return r;
}
__device__ __forceinline__ uint32_t smem_u32(const void* p) {
    uint32_t a;
    asm("{ .reg .u64 t; cvta.to.shared.u64 t, %1; cvt.u32.u64 %0, t; }"
        : "=r"(a) : "l"(p));
    return a;
}
__device__ __forceinline__ void cp16(uint32_t saddr, const void* g) {
    asm volatile("cp.async.ca.shared.global [%0], [%1], 16;"
                 :: "r"(saddr), "l"(g) : "memory");
}
__device__ __forceinline__ void cp_commit() {
    asm volatile("cp.async.commit_group;" ::: "memory");
}
__device__ __forceinline__ void cp_wait0() {
    asm volatile("cp.async.wait_group 0;" ::: "memory");
}

// -------- shared memory (union across phases) --------
struct SmP1 {
    float xrow[XCH * XPADW];  // staged x chunk, padded rows (34.8KB)
    float spw[61 * Dd];       // proj_w
    float spb[Dd];
};
struct SmP2 {
    ulonglong2 tile[2][160];  // [task][x(80)|e(80)] 16B chunks
    float ssq[32];            // per-tile-row ssq (2 tasks x 16 rows)
};
struct SmP3 {
    float sp[2][4 * PD];
    float sy[2][PD];
    float seh[2][HIDh];
    float semb[2][PD];
    float shq[2][SQq];
};
union SmemU {
    SmP1 p1;
    SmP2 p2;
    SmP3 p3;
};

// ============================================================
__global__ void __launch_bounds__(NTHR) fused_all(
        const float* __restrict__ x,
        const float* __restrict__ dc,
        const float* __restrict__ centers,
        const float* __restrict__ proj_w,
        const float* __restrict__ proj_b,
        const float* __restrict__ p_ptr,
        const float* __restrict__ cc,
        const float* __restrict__ gcn_w,
        const float* __restrict__ gcn_b,
        const float* __restrict__ out_w,
        const float* __restrict__ out_b,
        const float* __restrict__ w1,
        const float* __restrict__ b1,
        const float* __restrict__ w2,
        const float* __restrict__ b2,
        float* __restrict__ out) {
    __shared__ SmemU sm;
    __shared__ int slabel[32];

    int tid = threadIdx.x;
    int wid = tid >> 5, lane = tid & 31;
    int bx = blockIdx.x;
    int gt = bx * NTHR + tid;

    unsigned sense0 = 0;
    if (tid == 0) sense0 = g_bar_sense;

    float p = *p_ptr;
    float c1 = 1.0f - p;

    float* gx = (float*)g_x4;
    float* ge = (float*)g_e4;

    // ======================= P1: prep =======================
    {
        for (int i = tid; i < 61 * Dd; i += NTHR) sm.p1.spw[i] = proj_w[i];
        if (tid < Dd) sm.p1.spb[tid] = proj_b[tid];

        // e = exp(1 - dc) for patients
        for (int idx = gt; idx < Bp * Dd; idx += NT_ALL) {
            int b = idx / Dd, k = idx - b * Dd;
            ge[b * PD + k] = expf(1.0f - dc[idx]);
        }
        // pad slot = 0 for all rows
        for (int i = gt; i < Nn; i += NT_ALL) {
            gx[i * PD + Dd] = 0.0f;
            ge[i * PD + Dd] = 0.0f;
        }

        // x mean via smem-staged chunks: coalesced gmem, padded smem,
        // per-row tree reduction in the EXACT validated order.
        for (int ch = bx; ch < NCHUNK; ch += NBLK) {
            __syncthreads();     // previous chunk's readers done
            const float4* src = (const float4*)x + (size_t)ch * (XCH * 16);
            for (int i = tid; i < XCH * 16; i += NTHR) {
                int r = i >> 4, q = i & 15;
                *(float4*)&sm.p1.xrow[r * XPADW + q * 4] = src[i];
            }
            __syncthreads();
            if (tid < XCH) {
                const float* xr = &sm.p1.xrow[tid * XPADW];
                float xs[64];
                #pragma unroll
                for (int i = 0; i < 16; i++) {
                    float4 a = *(const float4*)&xr[i * 4];
                    xs[4 * i]     = a.x;
                    xs[4 * i + 1] = a.y;
                    xs[4 * i + 2] = a.z;
                    xs[4 * i + 3] = a.w;
                }
                float v[32];
                #pragma unroll
                for (int l = 0; l < 32; l++) v[l] = xs[l] + xs[l + 32];
                #pragma unroll
                for (int d = 16; d >= 1; d >>= 1) {
                    #pragma unroll
                    for (int l = 0; l < 16; l++) {
                        if (l < d) v[l] = v[l] + v[l + d];
                    }
                }
                int r = ch * XCH + tid;
                int b = r / Dd, d2 = r - b * Dd;
                gx[b * PD + d2] = v[0] * (1.0f / 64.0f);
            }
        }

        // centers spread over blocks; sequential-m per-center (bit-exact)
        __syncthreads();
        if ((tid == 0 || tid == 32)) {
            int c = bx + (tid >> 5) * NBLK;   // bx or bx+148
            if (c < NCc) {
                float cp[Dd];
                #pragma unroll
                for (int k = 0; k < Dd; k++) cp[k] = sm.p1.spb[k];
                for (int m = 0; m < 61; m++) {
                    float cm = centers[c * 61 + m];
                    #pragma unroll
                    for (int k = 0; k < Dd; k++) cp[k] += cm * sm.p1.spw[m * Dd + k];
                }
                int row = Bp + c;
                #pragma unroll
                for (int k = 0; k < Dd; k++) {
                    gx[row * PD + k] = cp[k];
                    ge[row * PD + k] = expf(1.0f - cc[c * Dd + k]);
                }
                gx[row * PD + Dd] = 0.0f;
                ge[row * PD + Dd] = 0.0f;
            }
        }
    }

    grid_barrier(&sense0);

    // ===== P2: lane = center (rows in registers, loaded ONCE); =====
    // ===== j-rows broadcast from smem; ssq precomputed per row; =====
    // ===== keys warp-min-reduced to 8 partials per patient.     =====
    {
        const ulonglong2* gxu = (const ulonglong2*)g_x4;
        const ulonglong2* geu = (const ulonglong2*)g_e4;
        int wc = wid & 7;        // center group: centers 32*wc + lane
        int jh = wid >> 3;       // j-half of the 16-j octant

        int cA = wc * 32 + lane;
        int cgA = Bp + cA;

        // stage both tasks' 16-row tiles (x and e) via cp.async
        {
            uint32_t sb = smem_u32(&sm.p2.tile[0][0]);
            for (int i = tid; i < 320; i += NTHR) {
                int ti = i / 160, rem = i - ti * 160;
                int which = rem / 80, idx = rem - which * 80;
                int t = bx + ti * NBLK;
                if (t < NTASK) {
                    int jt = t >> 3, oct = t & 7;
                    int grow = jt * JT + oct * 16 + idx / PD4;
                    const void* src = which
                        ? (const void*)(geu + grow * PD4 + (idx % PD4))
                        : (const void*)(gxu + grow * PD4 + (idx % PD4));
                    cp16(sb + (size_t)i * 16, src);
                }
            }
            cp_commit();
        }

        // center rows: registers, once
        ulonglong2 xA[PD4], eA[PD4];
        #pragma unroll
        for (int q = 0; q < PD4; q++) {
            xA[q] = gxu[cgA * PD4 + q];
            eA[q] = geu[cgA * PD4 + q];
        }
        // sqA: sequential scalar order over 19 elements (bit-exact)
        float sqA;
        {
            float fxA[PD];
            #pragma unroll
            for (int q = 0; q < PD4; q++) {
                fxA[4 * q]     = lo32(xA[q].x);
                fxA[4 * q + 1] = hi32(xA[q].x);
                fxA[4 * q + 2] = lo32(xA[q].y);
                fxA[4 * q + 3] = hi32(xA[q].y);
            }
            sqA = 0.0f;
            #pragma unroll
            for (int k = 0; k < Dd; k++) sqA += fxA[k] * fxA[k];
        }

        cp_wait0();
        __syncthreads();

        // precompute per-row ssq (sequential k order, bit-exact), once
        if (tid < 32) {
            int ti = tid >> 4, rj = tid & 15;
            int t = bx + ti * NBLK;
            if (t < NTASK) {
                const float* xr = (const float*)&sm.p2.tile[ti][rj * PD4];
                float ss = 0.0f;
                #pragma unroll
                for (int k = 0; k < Dd; k++) ss += xr[k] * xr[k];
                sm.p2.ssq[tid] = ss;
            }
        }
        __syncthreads();

        u64 yA[2 * PD4];
        #pragma unroll
        for (int m = 0; m < 2 * PD4; m++) yA[m] = 0ull;

        #pragma unroll
        for (int ti = 0; ti < 2; ti++) {
            int t = bx + ti * NBLK;
            if (t >= NTASK) break;
            int jt = t >> 3, oct = t & 7;
            bool ptile = (jt < NPJT);
            const ulonglong2* sx = &sm.p2.tile[ti][0];
            const ulonglong2* se = &sm.p2.tile[ti][80];

            #pragma unroll
            for (int jj = 0; jj < 8; jj++) {
                int rj = jh * 8 + jj;                    // row in tile
                int jgg = jt * JT + oct * 16 + rj;       // global row
                ulonglong2 vv[PD4], ww[PD4];
                #pragma unroll
                for (int q = 0; q < PD4; q++) {
                    vv[q] = sx[rj * PD4 + q];            // broadcast LDS
                    ww[q] = se[rj * PD4 + q];
                }
                float ssqj = sm.p2.ssq[ti * 16 + rj];    // broadcast

                u64 dxA2 = 0ull, deA2 = 0ull;
                #pragma unroll
                for (int q = 0; q < PD4; q++) {
                    ffma2(dxA2, xA[q].x, vv[q].x);  ffma2(dxA2, xA[q].y, vv[q].y);
                    ffma2(deA2, eA[q].x, ww[q].x);  ffma2(deA2, eA[q].y, ww[q].y);
                }
                float dxA = lo32(dxA2) + hi32(dxA2);
                float deA = lo32(deA2) + hi32(deA2);

                float denA = c1 * (sqA + ssqj - 2.0f * dxA) + p * deA;
                float aA = (jgg == cgA) ? 1.0f : __fdividef((float)Dd, denA);

                if (ptile) {
                    // warp-min over this warp's 32 centers (exact)
                    u64 km = (((u64)__float_as_uint(denA)) << 32) | (unsigned)cA;
                    u64 o;
                    o = __shfl_xor_sync(0xffffffffu, km, 1);  if (o < km) km = o;
                    o = __shfl_xor_sync(0xffffffffu, km, 2);  if (o < km) km = o;
                    o = __shfl_xor_sync(0xffffffffu, km, 4);  if (o < km) km = o;
                    o = __shfl_xor_sync(0xffffffffu, km, 8);  if (o < km) km = o;
                    o = __shfl_xor_sync(0xffffffffu, km, 16); if (o < km) km = o;
                    if (lane == 0) g_key8[(size_t)jgg * 8 + wc] = km;
                }

                u64 a2A = pack2(aA, aA);
                #pragma unroll
                for (int q = 0; q < PD4; q++) {
                    ffma2(yA[2 * q],     a2A, vv[q].x);
                    ffma2(yA[2 * q + 1], a2A, vv[q].y);
                }
            }
        }

        // one y-partial store per warp-lane: slot = (block, j-half)
        int slot = bx * 2 + jh;
        float4* dst = &g_party4[((size_t)slot * NCc + cA) * PD4];
        #pragma unroll
        for (int q = 0; q < PD4; q++) {
            float4 f;
            f.x = lo32(yA[2 * q]);      f.y = hi32(yA[2 * q]);
            f.z = lo32(yA[2 * q + 1]);  f.w = hi32(yA[2 * q + 1]);
            dst[q] = f;
        }
    }

    grid_barrier(&sense0);

    // ===== P4a: labels — min over 8 partial keys/patient (overlaps P3) =====
    if (bx < Bp / 32 && tid < 256) {
        int pl = tid >> 3, l8 = tid & 7;
        int jp = bx * 32 + pl;
        u64 best = g_key8[(size_t)jp * 8 + l8];
        u64 o;
        o = __shfl_xor_sync(0xffffffffu, best, 1); if (o < best) best = o;
        o = __shfl_xor_sync(0xffffffffu, best, 2); if (o < best) best = o;
        o = __shfl_xor_sync(0xffffffffu, best, 4); if (o < best) best = o;
        if (l8 == 0) slabel[pl] = (int)(unsigned)(best & 0xFFFFFFFFull);
    }

    // ======================= P3: center MLP chain =======================
    if (wid < 8) {
        int half = wid >> 2;                 // 0/1
        int w4 = wid & 3;
        int c = bx * 2 + half;
        bool active = (bx < NCc / 2);

        float ps = 0.0f;
        if (active && lane < PD) {
            int s0 = w4 * 74;                // 296 slots = 4 x 74
            const float* pp = (const float*)g_party4 + (size_t)c * PD + lane;
            for (int sl = s0; sl < s0 + 74; sl++)
                ps += pp[(size_t)sl * (NCc * PD)];
        }
        if (lane < PD) sm.p3.sp[half][w4 * PD + lane] = ps;
    }
    __syncthreads();

    if (wid < 8) {
        int half = wid >> 2;
        int w4 = wid & 3;
        int c = bx * 2 + half;
        bool active = (bx < NCc / 2);

        if (w4 == 0 && active) {
            int h = lane;
            if (lane < PD) {
                const float* spv = sm.p3.sp[half];
                sm.p3.sy[half][lane] = spv[lane] + spv[PD + lane]
                                     + spv[2 * PD + lane] + spv[3 * PD + lane];
            }
            __syncwarp();

            float eh = gcn_b[h];
            #pragma unroll
            for (int k = 0; k < Dd; k++)
                eh += sm.p3.sy[half][k] * gcn_w[k * HIDh + h];
            sm.p3.seh[half][h] = eh;
            __syncwarp();

            if (h < Dd) {
                float v = out_b[h];
                #pragma unroll
                for (int q = 0; q < HIDh; q++) v += sm.p3.seh[half][q] * out_w[q * Dd + h];
                v = 1.0f / (1.0f + expf(-v));
                sm.p3.semb[half][h] = v;
                g_ge[c * Dd + h] = v;
                out[OUT_GE + c * Dd + h] = v;
            }
            __syncwarp();

            if (h < SQq) {
                float v = b1[h];
                #pragma unroll
                for (int k = 0; k < Dd; k++) v += sm.p3.semb[half][k] * w1[k * SQq + h];
                sm.p3.shq[half][h] = 0.5f * v * (1.0f + erff(v * 0.70710678118654752f));
            }
            __syncwarp();

            if (h < Dd) {
                float v = b2[h];
                #pragma unroll
                for (int q = 0; q < SQq; q++) v += sm.p3.shq[half][q] * w2[q * Dd + h];
                g_sc[c * Dd + h] = 1.0f / (1.0f + expf(-v));
            }
        }
    }

    grid_barrier(&sense0);

    // ======================= P4b: gather =======================
    if (bx < Bp / 32 && tid < 256) {
        int pl = tid >> 3, l8 = tid & 7;
        int jp = bx * 32 + pl;
        int label = slabel[pl];
        #pragma unroll
        for (int k = l8; k < Dd; k += 8) {
            out[OUT_GS + jp * Dd + k]  = g_sc[label * Dd + k];
            out[OUT_GPE + jp * Dd + k] = g_ge[label * Dd + k];
        }
        if (l8 == 0) out[OUT_GL + jp] = (float)label;
    }
}

// ============================================================
extern "C" void kernel_launch(void* const* d_in, const int* in_sizes, int n_in,
                              void* d_out, int out_size) {
    const float* x        = (const float*)d_in[0];
    const float* dc       = (const float*)d_in[1];
    const float* centers  = (const float*)d_in[2];
    const float* proj_w   = (const float*)d_in[3];
    const float* proj_b   = (const float*)d_in[4];
    const float* dc_param = (const float*)d_in[5];
    const float* cc       = (const float*)d_in[6];
    const float* gcn_w    = (const float*)d_in[7];
    const float* gcn_b    = (const float*)d_in[8];
    const float* out_w    = (const float*)d_in[9];
    const float* out_b    = (const float*)d_in[10];
    const float* w1       = (const float*)d_in[11];
    const float* b1       = (const float*)d_in[12];
    const float* w2       = (const float*)d_in[13];
    const float* b2       = (const float*)d_in[14];
    float* out = (float*)d_out;

    fused_all<<<NBLK, NTHR>>>(x, dc, centers, proj_w, proj_b, dc_param, cc,
                              gcn_w, gcn_b, out_w, out_b, w1, b1, w2, b2, out);
}

// round 17
// speedup vs baseline: 1.1221x; 1.1221x over previous
#include <cuda_runtime.h>
#include <cstdint>
#include <math.h>

// Problem constants
#define Bp   4096
#define Dd   19
#define Ff   64
#define NCc  256
#define HIDh 32
#define SQq  16
#define Nn   (Bp + NCc)
#define PD   20            // padded row stride (19 + 1 zero pad)
#define PD4  5             // PD/4 (float4 granules)

// P2 tiling: task = (jt, oct of 16 j's). Lane = center. Static 2 tasks/block.
#define JT   128
#define NJT  (Nn / JT)      // 34
#define NPJT (Bp / JT)      // 32 patient-only tiles
#define NTASK (NJT * 8)     // 272 (16-j octants)
#define NSLOT (2 * 148)     // 296 y-partial slots: (block, j-half)

// Persistent grid
#define NBLK 148
#define NTHR 512
#define NT_ALL (NBLK * NTHR)       // 75776
#define NROW  (Bp * Dd)            // 77824 x-rows
#define XW    14                   // warps 2..15 do x-mean
#define XSTRIDE (NBLK * XW)        // 2072
#define EW    448                  // threads 64..511 do e/pad writes
#define ESTRIDE (NBLK * EW)        // 66304

// Output offsets (floats)
#define OUT_GS  0
#define OUT_GE  (Bp * Dd)
#define OUT_GPE ((Bp + NCc) * Dd)
#define OUT_GL  (((2 * Bp) + NCc) * Dd)

typedef unsigned long long u64;

// -------- device scratch (no allocations allowed) --------
__device__ float4 g_x4[Nn * PD4];
__device__ float4 g_e4[Nn * PD4];
__device__ float4 g_party4[NSLOT * NCc * PD4];  // y-partials [slot][center][5]
__device__ u64    g_key8[(size_t)Bp * 8];       // [patient][wc-group] partial keys
__device__ float  g_ge[NCc * Dd];
__device__ float  g_sc[NCc * Dd];

// grid barrier state (zero-init at load; returns to steady state each run)
__device__ unsigned g_cnt[8];
__device__ unsigned g_cnt_root;
__device__ volatile unsigned g_bar_sense;

// Two-level sense-reversal barrier: 8 group counters -> root counter.
__device__ __forceinline__ void grid_barrier(unsigned* sense0) {
    __syncthreads();
    if (threadIdx.x == 0) {
        unsigned next = *sense0 ^ 1u;
        __threadfence();                       // publish this block's writes
        int g = blockIdx.x & 7;
        unsigned gsz = (g < 4) ? 19u : 18u;    // 148 = 4*19 + 4*18
        if (atomicAdd(&g_cnt[g], 1u) == gsz - 1u) {
            if (atomicAdd(&g_cnt_root, 1u) == 7u) {
                g_cnt_root = 0u;
                #pragma unroll
                for (int i = 0; i < 8; i++) g_cnt[i] = 0u;
                __threadfence();
                g_bar_sense = next;
            }
        }
        while (g_bar_sense != next) { }
        __threadfence();                       // acquire side
        *sense0 = next;
    }
    __syncthreads();
}

// packed f32x2 fma: d = a*b + d
__device__ __forceinline__ void ffma2(u64& d, u64 a, u64 b) {
    asm("fma.rn.f32x2 %0, %1, %2, %0;" : "+l"(d) : "l"(a), "l"(b));
}
__device__ __forceinline__ float lo32(u64 v) {
    return __uint_as_float((unsigned)(v & 0xFFFFFFFFull));
}
__device__ __forceinline__ float hi32(u64 v) {
    return __uint_as_float((unsigned)(v >> 32));
}
__device__ __forceinline__ u64 pack2(float a, float b) {
    u64 r;
    asm("mov.b64 %0, {%1, %2};" : "=l"(r) : "r"(__float_as_uint(a)), "r"(__float_as_uint(b)));
    return r;
}
__device__ __forceinline__ uint32_t smem_u32(const void* p) {
    uint32_t a;
    asm("{ .reg .u64 t; cvta.to.shared.u64 t, %1; cvt.u32.u64 %0, t; }"
        : "=r"(a) : "l"(p));
    return a;
}
__device__ __forceinline__ void cp16(uint32_t saddr, const void* g) {
    asm volatile("cp.async.ca.shared.global [%0], [%1], 16;"
                 :: "r"(saddr), "l"(g) : "memory");
}
__device__ __forceinline__ void cp_commit() {
    asm volatile("cp.async.commit_group;" ::: "memory");
}
__device__ __forceinline__ void cp_wait0() {
    asm volatile("cp.async.wait_group 0;" ::: "memory");
}

// -------- shared memory (union across phases) --------
struct SmP1 {
    float spw[61 * Dd];       // proj_w (staged by warps 0-1)
    float spb[Dd];
};
struct SmP2 {
    ulonglong2 tile[2][160];  // [task][x(80)|e(80)] 16B chunks
    float ssq[32];            // per-tile-row ssq (2 tasks x 16 rows)
};
struct SmP3 {
    float sp[2][4 * PD];
    float sy[2][PD];
    float seh[2][HIDh];
    float semb[2][PD];
    float shq[2][SQq];
};
union SmemU {
    SmP1 p1;
    SmP2 p2;
    SmP3 p3;
};

// ============================================================
__global__ void __launch_bounds__(NTHR) fused_all(
        const float* __restrict__ x,
        const float* __restrict__ dc,
        const float* __restrict__ centers,
        const float* __restrict__ proj_w,
        const float* __restrict__ proj_b,
        const float* __restrict__ p_ptr,
        const float* __restrict__ cc,
        const float* __restrict__ gcn_w,
        const float* __restrict__ gcn_b,
        const float* __restrict__ out_w,
        const float* __restrict__ out_b,
        const float* __restrict__ w1,
        const float* __restrict__ b1,
        const float* __restrict__ w2,
        const float* __restrict__ b2,
        float* __restrict__ out) {
    __shared__ SmemU sm;
    __shared__ int slabel[32];

    int tid = threadIdx.x;
    int wid = tid >> 5, lane = tid & 31;
    int bx = blockIdx.x;

    unsigned sense0 = 0;
    if (tid == 0) sense0 = g_bar_sense;

    float p = *p_ptr;
    float c1 = 1.0f - p;

    float* gx = (float*)g_x4;
    float* ge = (float*)g_e4;

    // ======================= P1: prep =======================
    // Warps 0-1: center projection (overlapped with x-mean on warps 2-15).
    // Warps 2-15: x-mean (warp-per-row, coalesced, exact shfl-tree order),
    //             then e = exp(1-dc) and pad writes.
    if (wid < 2) {
        // stage proj_w/proj_b with these 64 threads only
        for (int i = tid; i < 61 * Dd; i += 64) sm.p1.spw[i] = proj_w[i];
        if (tid < Dd) sm.p1.spb[tid] = proj_b[tid];
        asm volatile("bar.sync 1, 64;" ::: "memory");   // warps 0-1 only

        if (lane == 0) {
            int c = bx + wid * NBLK;          // bx or bx+148
            if (c < NCc) {
                float cp[Dd];
                #pragma unroll
                for (int k = 0; k < Dd; k++) cp[k] = sm.p1.spb[k];
                for (int m = 0; m < 61; m++) {
                    float cm = centers[c * 61 + m];
                    #pragma unroll
                    for (int k = 0; k < Dd; k++) cp[k] += cm * sm.p1.spw[m * Dd + k];
                }
                int row = Bp + c;
                #pragma unroll
                for (int k = 0; k < Dd; k++) {
                    gx[row * PD + k] = cp[k];
                    ge[row * PD + k] = expf(1.0f - cc[c * Dd + k]);
                }
                gx[row * PD + Dd] = 0.0f;
                ge[row * PD + Dd] = 0.0f;
            }
        }
    } else {
        // x mean: warp per row; lane loads x[lane], x[lane+32] (coalesced),
        // shfl_down tree 16/8/4/2/1 — EXACT validated reduction order.
        for (int r = bx * XW + (wid - 2); r < NROW; r += XSTRIDE) {
            const float* xr = x + (size_t)r * Ff;
            float v = xr[lane] + xr[lane + 32];
            v += __shfl_down_sync(0xffffffffu, v, 16);
            v += __shfl_down_sync(0xffffffffu, v, 8);
            v += __shfl_down_sync(0xffffffffu, v, 4);
            v += __shfl_down_sync(0xffffffffu, v, 2);
            v += __shfl_down_sync(0xffffffffu, v, 1);
            if (lane == 0) {
                int b = r / Dd, d2 = r - b * Dd;
                gx[b * PD + d2] = v * (1.0f / 64.0f);
            }
        }

        // e = exp(1 - dc) for patients (threads 64..511)
        int et = bx * EW + (tid - 64);
        for (int idx = et; idx < Bp * Dd; idx += ESTRIDE) {
            int b = idx / Dd, k = idx - b * Dd;
            ge[b * PD + k] = expf(1.0f - dc[idx]);
        }
        // pad slot = 0 for all rows
        for (int i = et; i < Nn; i += ESTRIDE) {
            gx[i * PD + Dd] = 0.0f;
            ge[i * PD + Dd] = 0.0f;
        }
    }

    grid_barrier(&sense0);

    // ===== P2: lane = center (rows in registers, loaded ONCE); =====
    // ===== j-rows broadcast from smem; ssq precomputed per row; =====
    // ===== keys warp-min-reduced to 8 partials per patient.     =====
    {
        const ulonglong2* gxu = (const ulonglong2*)g_x4;
        const ulonglong2* geu = (const ulonglong2*)g_e4;
        int wc = wid & 7;        // center group: centers 32*wc + lane
        int jh = wid >> 3;       // j-half of the 16-j octant

        int cA = wc * 32 + lane;
        int cgA = Bp + cA;

        // stage both tasks' 16-row tiles (x and e) via cp.async
        {
            uint32_t sb = smem_u32(&sm.p2.tile[0][0]);
            for (int i = tid; i < 320; i += NTHR) {
                int ti = i / 160, rem = i - ti * 160;
                int which = rem / 80, idx = rem - which * 80;
                int t = bx + ti * NBLK;
                if (t < NTASK) {
                    int jt = t >> 3, oct = t & 7;
                    int grow = jt * JT + oct * 16 + idx / PD4;
                    const void* src = which
                        ? (const void*)(geu + grow * PD4 + (idx % PD4))
                        : (const void*)(gxu + grow * PD4 + (idx % PD4));
                    cp16(sb + (size_t)i * 16, src);
                }
            }
            cp_commit();
        }

        // center rows: registers, once
        ulonglong2 xA[PD4], eA[PD4];
        #pragma unroll
        for (int q = 0; q < PD4; q++) {
            xA[q] = gxu[cgA * PD4 + q];
            eA[q] = geu[cgA * PD4 + q];
        }
        // sqA: sequential scalar order over 19 elements (bit-exact)
        float sqA;
        {
            float fxA[PD];
            #pragma unroll
            for (int q = 0; q < PD4; q++) {
                fxA[4 * q]     = lo32(xA[q].x);
                fxA[4 * q + 1] = hi32(xA[q].x);
                fxA[4 * q + 2] = lo32(xA[q].y);
                fxA[4 * q + 3] = hi32(xA[q].y);
            }
            sqA = 0.0f;
            #pragma unroll
            for (int k = 0; k < Dd; k++) sqA += fxA[k] * fxA[k];
        }

        cp_wait0();
        __syncthreads();

        // precompute per-row ssq (sequential k order, bit-exact), once
        if (tid < 32) {
            int ti = tid >> 4, rj = tid & 15;
            int t = bx + ti * NBLK;
            if (t < NTASK) {
                const float* xr = (const float*)&sm.p2.tile[ti][rj * PD4];
                float ss = 0.0f;
                #pragma unroll
                for (int k = 0; k < Dd; k++) ss += xr[k] * xr[k];
                sm.p2.ssq[tid] = ss;
            }
        }
        __syncthreads();

        u64 yA[2 * PD4];
        #pragma unroll
        for (int m = 0; m < 2 * PD4; m++) yA[m] = 0ull;

        #pragma unroll
        for (int ti = 0; ti < 2; ti++) {
            int t = bx + ti * NBLK;
            if (t >= NTASK) break;
            int jt = t >> 3, oct = t & 7;
            bool ptile = (jt < NPJT);
            const ulonglong2* sx = &sm.p2.tile[ti][0];
            const ulonglong2* se = &sm.p2.tile[ti][80];

            #pragma unroll
            for (int jj = 0; jj < 8; jj++) {
                int rj = jh * 8 + jj;                    // row in tile
                int jgg = jt * JT + oct * 16 + rj;       // global row
                ulonglong2 vv[PD4], ww[PD4];
                #pragma unroll
                for (int q = 0; q < PD4; q++) {
                    vv[q] = sx[rj * PD4 + q];            // broadcast LDS
                    ww[q] = se[rj * PD4 + q];
                }
                float ssqj = sm.p2.ssq[ti * 16 + rj];    // broadcast

                u64 dxA2 = 0ull, deA2 = 0ull;
                #pragma unroll
                for (int q = 0; q < PD4; q++) {
                    ffma2(dxA2, xA[q].x, vv[q].x);  ffma2(dxA2, xA[q].y, vv[q].y);
                    ffma2(deA2, eA[q].x, ww[q].x);  ffma2(deA2, eA[q].y, ww[q].y);
                }
                float dxA = lo32(dxA2) + hi32(dxA2);
                float deA = lo32(deA2) + hi32(deA2);

                float denA = c1 * (sqA + ssqj - 2.0f * dxA) + p * deA;
                float aA = (jgg == cgA) ? 1.0f : __fdividef((float)Dd, denA);

                if (ptile) {
                    // warp-min over this warp's 32 centers (exact)
                    u64 km = (((u64)__float_as_uint(denA)) << 32) | (unsigned)cA;
                    u64 o;
                    o = __shfl_xor_sync(0xffffffffu, km, 1);  if (o < km) km = o;
                    o = __shfl_xor_sync(0xffffffffu, km, 2);  if (o < km) km = o;
                    o = __shfl_xor_sync(0xffffffffu, km, 4);  if (o < km) km = o;
                    o = __shfl_xor_sync(0xffffffffu, km, 8);  if (o < km) km = o;
                    o = __shfl_xor_sync(0xffffffffu, km, 16); if (o < km) km = o;
                    if (lane == 0) g_key8[(size_t)jgg * 8 + wc] = km;
                }

                u64 a2A = pack2(aA, aA);
                #pragma unroll
                for (int q = 0; q < PD4; q++) {
                    ffma2(yA[2 * q],     a2A, vv[q].x);
                    ffma2(yA[2 * q + 1], a2A, vv[q].y);
                }
            }
        }

        // one y-partial store per warp-lane: slot = (block, j-half)
        int slot = bx * 2 + jh;
        float4* dst = &g_party4[((size_t)slot * NCc + cA) * PD4];
        #pragma unroll
        for (int q = 0; q < PD4; q++) {
            float4 f;
            f.x = lo32(yA[2 * q]);      f.y = hi32(yA[2 * q]);
            f.z = lo32(yA[2 * q + 1]);  f.w = hi32(yA[2 * q + 1]);
            dst[q] = f;
        }
    }

    grid_barrier(&sense0);

    // ===== P4a: labels — min over 8 partial keys/patient (overlaps P3) =====
    if (bx < Bp / 32 && tid < 256) {
        int pl = tid >> 3, l8 = tid & 7;
        int jp = bx * 32 + pl;
        u64 best = g_key8[(size_t)jp * 8 + l8];
        u64 o;
        o = __shfl_xor_sync(0xffffffffu, best, 1); if (o < best) best = o;
        o = __shfl_xor_sync(0xffffffffu, best, 2); if (o < best) best = o;
        o = __shfl_xor_sync(0xffffffffu, best, 4); if (o < best) best = o;
        if (l8 == 0) slabel[pl] = (int)(unsigned)(best & 0xFFFFFFFFull);
    }

    // ======================= P3: center MLP chain =======================
    if (wid < 8) {
        int half = wid >> 2;                 // 0/1
        int w4 = wid & 3;
        int c = bx * 2 + half;
        bool active = (bx < NCc / 2);

        float ps = 0.0f;
        if (active && lane < PD) {
            int s0 = w4 * 74;                // 296 slots = 4 x 74
            const float* pp = (const float*)g_party4 + (size_t)c * PD + lane;
            for (int sl = s0; sl < s0 + 74; sl++)
                ps += pp[(size_t)sl * (NCc * PD)];
        }
        if (lane < PD) sm.p3.sp[half][w4 * PD + lane] = ps;
    }
    __syncthreads();

    if (wid < 8) {
        int half = wid >> 2;
        int w4 = wid & 3;
        int c = bx * 2 + half;
        bool active = (bx < NCc / 2);

        if (w4 == 0 && active) {
            int h = lane;
            if (lane < PD) {
                const float* spv = sm.p3.sp[half];
                sm.p3.sy[half][lane] = spv[lane] + spv[PD + lane]
                                     + spv[2 * PD + lane] + spv[3 * PD + lane];
            }
            __syncwarp();

            float eh = gcn_b[h];
            #pragma unroll
            for (int k = 0; k < Dd; k++)
                eh += sm.p3.sy[half][k] * gcn_w[k * HIDh + h];
            sm.p3.seh[half][h] = eh;
            __syncwarp();

            if (h < Dd) {
                float v = out_b[h];
                #pragma unroll
                for (int q = 0; q < HIDh; q++) v += sm.p3.seh[half][q] * out_w[q * Dd + h];
                v = 1.0f / (1.0f + expf(-v));
                sm.p3.semb[half][h] = v;
                g_ge[c * Dd + h] = v;
                out[OUT_GE + c * Dd + h] = v;
            }
            __syncwarp();

            if (h < SQq) {
                float v = b1[h];
                #pragma unroll
                for (int k = 0; k < Dd; k++) v += sm.p3.semb[half][k] * w1[k * SQq + h];
                sm.p3.shq[half][h] = 0.5f * v * (1.0f + erff(v * 0.70710678118654752f));
            }
            __syncwarp();

            if (h < Dd) {
                float v = b2[h];
                #pragma unroll
                for (int q = 0; q < SQq; q++) v += sm.p3.shq[half][q] * w2[q * Dd + h];
                g_sc[c * Dd + h] = 1.0f / (1.0f + expf(-v));
            }
        }
    }

    grid_barrier(&sense0);

    // ======================= P4b: gather =======================
    if (bx < Bp / 32 && tid < 256) {
        int pl = tid >> 3, l8 = tid & 7;
        int jp = bx * 32 + pl;
        int label = slabel[pl];
        #pragma unroll
        for (int k = l8; k < Dd; k += 8) {
            out[OUT_GS + jp * Dd + k]  = g_sc[label * Dd + k];
            out[OUT_GPE + jp * Dd + k] = g_ge[label * Dd + k];
        }
        if (l8 == 0) out[OUT_GL + jp] = (float)label;
    }
}

// ============================================================
extern "C" void kernel_launch(void* const* d_in, const int* in_sizes, int n_in,
                              void* d_out, int out_size) {
    const float* x        = (const float*)d_in[0];
    const float* dc       = (const float*)d_in[1];
    const float* centers  = (const float*)d_in[2];
    const float* proj_w   = (const float*)d_in[3];
    const float* proj_b   = (const float*)d_in[4];
    const float* dc_param = (const float*)d_in[5];
    const float* cc       = (const float*)d_in[6];
    const float* gcn_w    = (const float*)d_in[7];
    const float* gcn_b    = (const float*)d_in[8];
    const float* out_w    = (const float*)d_in[9];
    const float* out_b    = (const float*)d_in[10];
    const float* w1       = (const float*)d_in[11];
    const float* b1       = (const float*)d_in[12];
    const float* w2       = (const float*)d_in[13];
    const float* b2       = (const float*)d_in[14];
    float* out = (float*)d_out;

    fused_all<<<NBLK, NTHR>>>(x, dc, centers, proj_w, proj_b, dc_param, cc,
                              gcn_w, gcn_b, out_w, out_b, w1, b1, w2, b2, out);
}